// round 11
// baseline (speedup 1.0000x reference)
#include <cuda_runtime.h>

#define Bn 16
#define Tn 192
#define Un 64
#define Hn 512
#define NEGF (-1e30f)
#define LOG2E 1.4426950408889634f
#define LN2f  0.6931471805599453f

// Diagonal-major fused table, base-2 log domain.
// Cell (t,u) lives at row d = t+u, col u, as float2:
//   .x = lpb2[t-1][u], .y = lpl2[t][u-1]. OOR cells = NEGF (written by t==0 blocks).
__device__ float g_cd[Bn * 256 * Un * 2];
// Per-(b,t) completion counters (4 q-blocks each). Reset in-kernel for graph replay.
__device__ int g_cnt[Bn * Tn];

__device__ __forceinline__ float warpMax(float v) {
#pragma unroll
    for (int o = 16; o > 0; o >>= 1)
        v = fmaxf(v, __shfl_xor_sync(0xffffffffu, v, o));
    return v;
}
__device__ __forceinline__ float warpSum(float v) {
#pragma unroll
    for (int o = 16; o > 0; o >>= 1)
        v += __shfl_xor_sync(0xffffffffu, v, o);
    return v;
}
__device__ __forceinline__ float ex2f(float x) {
    float r; asm("ex2.approx.ftz.f32 %0, %1;" : "=f"(r) : "f"(x)); return r;
}
__device__ __forceinline__ float lg2f(float x) {
    float r; asm("lg2.approx.ftz.f32 %0, %1;" : "=f"(r) : "f"(x)); return r;
}
__device__ __forceinline__ float laddexp2(float a, float b) {
    float m = fmaxf(a, b);
    float t = ex2f(-fabsf(a - b));
    return m + lg2f(1.0f + t);
}
// LDS.128 via asm volatile: not hoistable above the volatile flag-poll loop.
__device__ __forceinline__ float4 lds128v(const float* p) {
    float4 v; unsigned a = (unsigned)__cvta_generic_to_shared(p);
    asm volatile("ld.shared.v4.f32 {%0,%1,%2,%3}, [%4];"
                 : "=f"(v.x), "=f"(v.y), "=f"(v.z), "=f"(v.w) : "r"(a));
    return v;
}
__device__ __forceinline__ float extract_elem(
    const float4& v0, const float4& v1, const float4& v2, const float4& v3, int e) {
    int g = (e >> 7) & 3;
    int comp = e & 3;
    int srclane = (e >> 2) & 31;
    float4 vv = (g == 0) ? v0 : (g == 1) ? v1 : (g == 2) ? v2 : v3;
    float c = (comp == 0) ? vv.x : (comp == 1) ? vv.y : (comp == 2) ? vv.z : vv.w;
    return __shfl_sync(0xffffffffu, c, srclane);
}

#define SM_RING_F   (64 * Un * 2)              /* 8192 floats = 32 KB ring   */
#define SMEM_BYTES  (SM_RING_F * 4 + 258 * 4)  /* + flags[256] + W + cons    */

__global__ __launch_bounds__(512, 4)
void k_fused(const float* __restrict__ x,
             const int* __restrict__ label,
             const int* __restrict__ f_len,
             const int* __restrict__ y_len,
             const int* __restrict__ blankp,
             float* __restrict__ out) {
    extern __shared__ float sm[];
    float* ring = sm;                                  // 64 rows x 512 B
    int* s_flag = (int*)(sm + SM_RING_F);              // [256]
    volatile int* s_W    = (volatile int*)(s_flag + 256);
    volatile int* s_cons = (volatile int*)(s_flag + 257);

    const int bid = blockIdx.x;
    const int tid = threadIdx.x;
    const int warp = tid >> 5;
    const int lane = tid & 31;

    if (bid >= Bn) {
        // ================= LSE role (bt-major, same as the 74.2us k_lse) ===
        const int bid2 = bid - Bn;
        const int bt = bid2 >> 2;                      // b*Tn + t
        const int q = bid2 & 3;
        const int b = bt / Tn;
        const int t = bt - b * Tn;
        const int u = (q << 4) + warp;                 // 0..63
        const int blank = blankp ? __ldg(blankp) : 0;

        float* const base = g_cd + (size_t)b * 256 * Un * 2;

        // NEGF init of unwritten cells (t==0 blocks only; disjoint writes)
        if (t == 0) {
#pragma unroll
            for (int h = 0; h < 2; h++) {
                int rr = lane + h * 32;                    // 0..63
                int rx = (rr <= u) ? rr : rr + 192;        // .x unwritten rows
                base[(rx * Un + u) * 2 + 0] = NEGF;
                if (u >= 1) {
                    int ry = (rr < u) ? rr : rr + 192;     // .y unwritten rows
                    base[(ry * Un + u) * 2 + 1] = NEGF;
                }
            }
            if (u == 0) {
#pragma unroll
                for (int h = 0; h < 8; h++)                // col 0 .y: all rows
                    base[((lane + h * 32) * Un) * 2 + 1] = NEGF;
            }
        }

        const float4* r = reinterpret_cast<const float4*>(x)
                          + ((size_t)bt * Un + u) * (Hn / 4);
        float4 a0 = __ldcs(r + lane);
        float4 a1 = __ldcs(r + lane + 32);
        float4 a2 = __ldcs(r + lane + 64);
        float4 a3 = __ldcs(r + lane + 96);

        int lab = (u < Un - 1) ? __ldg(&label[b * (Un - 1) + u]) : 0;

        float m = fmaxf(fmaxf(fmaxf(a0.x, a0.y), fmaxf(a0.z, a0.w)),
                 fmaxf(fmaxf(fmaxf(a1.x, a1.y), fmaxf(a1.z, a1.w)),
                 fmaxf(fmaxf(fmaxf(a2.x, a2.y), fmaxf(a2.z, a2.w)),
                       fmaxf(fmaxf(a3.x, a3.y), fmaxf(a3.z, a3.w)))));
        m = warpMax(m);
        float s = __expf(a0.x - m) + __expf(a0.y - m) + __expf(a0.z - m) + __expf(a0.w - m)
                + __expf(a1.x - m) + __expf(a1.y - m) + __expf(a1.z - m) + __expf(a1.w - m)
                + __expf(a2.x - m) + __expf(a2.y - m) + __expf(a2.z - m) + __expf(a2.w - m)
                + __expf(a3.x - m) + __expf(a3.y - m) + __expf(a3.z - m) + __expf(a3.w - m);
        s = warpSum(s);
        float denom = m + __logf(s);

        float xb = extract_elem(a0, a1, a2, a3, blank);
        float xl = extract_elem(a0, a1, a2, a3, lab);
        if (lane == 0) {
            base[(((t + u + 1) * Un) + u) * 2 + 0] = (xb - denom) * LOG2E;
            if (u < Un - 1)
                base[(((t + u + 1) * Un) + u + 1) * 2 + 1] = (xl - denom) * LOG2E;
        }
        // block-aggregated release: ONE fence + atomic per block (not per warp)
        __syncthreads();
        if (tid == 0) {
            __threadfence();
            atomicAdd(&g_cnt[bt], 1);
        }
        return;
    }

    // ================= ALPHA role (b = bid) =================
    const int b = bid;
    if (tid < 256) s_flag[tid] = 0;
    if (tid == 256) *s_W = -1;
    if (tid == 257) *s_cons = 0;
    __syncthreads();

    const float* gb = g_cd + (size_t)b * 256 * Un * 2;

    if (warp == 9) {
        // scanner: contiguous watermark over g_cnt[b][0..191] (target 4/row),
        // then reset counters for the next graph replay.
        int* cb = g_cnt + b * Tn;
        int W = -1;
        while (W < Tn - 1) {
            int idx = W + 1 + lane;
            int done = (idx < Tn) ? ((*(volatile int*)(cb + idx)) == 4) : 1;
            unsigned mk = __ballot_sync(0xffffffffu, done);
            int adv = __ffs(~mk) - 1;
            if (adv < 0) adv = 32;
            if (adv == 0) { __nanosleep(200); continue; }
            W += adv;
            __threadfence();                       // acquire before publish
            if (lane == 0) *s_W = W;
        }
        for (int i = lane; i < Tn; i += 32) cb[i] = 0;
        return;
    }
    if (warp >= 1 && warp <= 8) {
        // copier: rows rr = (warp-1) + 8k into ring slot rr & 63
#pragma unroll 1
        for (int k = 0; k < 32; k++) {
            int rr = (warp - 1) + (k << 3);
            int need = min(rr, Tn - 1);
            while (*s_W < need) __nanosleep(100);
            while (rr - 63 > *s_cons) __nanosleep(100);
            __threadfence_block();
            float4 v = *((const float4*)(gb + rr * (Un * 2)) + lane);
            *((float4*)(ring + (rr & 63) * (Un * 2)) + lane) = v;
            __threadfence_block();
            __syncwarp();
            if (lane == 0) *(volatile int*)(s_flag + rr) = 1;
        }
        return;
    }
    if (warp != 0) return;

    // consumer (warp 0): wavefront, 2 u-cells/lane, flag-gated ring reads
    const int tl = f_len[b] - 1;                 // 95..191
    const int ul = y_len[b];                     // 32..63
    const int dHit = tl + ul;                    // <= 254
    const unsigned FULL = 0xffffffffu;

    while (*(volatile int*)(s_flag + 1) == 0) __nanosleep(50);
    float4 c = lds128v(ring + (1 & 63) * (Un * 2) + lane * 4);
    float aA = 0.f, aB = 0.f;                    // lane0: alpha2[0][0] = 0

#pragma unroll 2
    for (int d = 1; d <= dHit; d++) {
        while (*(volatile int*)(s_flag + d + 1) == 0) __nanosleep(50);
        float4 cn = lds128v(ring + ((d + 1) & 63) * (Un * 2) + lane * 4);
        float lA = __shfl_up_sync(FULL, aB, 1);  // lane0: dead (c.y == NEGF)
        float lB = aA;
        float nA = laddexp2(aA + c.x, lA + c.y);
        float nB = laddexp2(aB + c.z, lB + c.w);
        aA = nA;
        aB = nB;
        c = cn;
        if (((d & 15) == 0) && lane == 0) *s_cons = d;
    }

    if (lane == 0) *s_cons = 255;                // release copiers (exit)
    if (lane == (ul >> 1)) {
        float v  = (ul & 1) ? aB : aA;
        float fb = (ul & 1) ? c.z : c.x;         // c == row dHit+1: lpb2[tl][ul]
        out[b] = -(v + fb) * LN2f;
    }
}

extern "C" void kernel_launch(void* const* d_in, const int* in_sizes, int n_in,
                              void* d_out, int out_size) {
    const float* x = (const float*)d_in[0];
    const int* label = (const int*)d_in[1];
    const int* f_len = (const int*)d_in[2];
    const int* y_len = (const int*)d_in[3];
    const int* blankp = (n_in > 4) ? (const int*)d_in[4] : nullptr;

    cudaFuncSetAttribute(k_fused, cudaFuncAttributeMaxDynamicSharedMemorySize,
                         SMEM_BYTES);
    k_fused<<<Bn + Bn * Tn * 4, 512, SMEM_BYTES>>>(x, label, f_len, y_len,
                                                   blankp, (float*)d_out);
}

// round 12
// speedup vs baseline: 1.1099x; 1.1099x over previous
#include <cuda_runtime.h>

#define Bn 16
#define Tn 192
#define Un 64
#define Hn 512
#define NEGF (-1e30f)
#define LOG2E 1.4426950408889634f
#define LN2f  0.6931471805599453f

// Diagonal-major fused table, base-2 log domain.
// Cell (t,u) lives at row d = t+u, col u, as float2:
//   .x = lpb2[t-1][u]  (the "up" transition into (t,u))
//   .y = lpl2[t][u-1]  (the "left" transition into (t,u))
// Rows 0..255; cells never written by k_lse are set to NEGF by the t==0
// blocks of k_lse itself (disjoint addresses -> no race, no extra launch).
__device__ float g_cd[Bn * 256 * Un * 2];

__device__ __forceinline__ float warpMax(float v) {
#pragma unroll
    for (int o = 16; o > 0; o >>= 1)
        v = fmaxf(v, __shfl_xor_sync(0xffffffffu, v, o));
    return v;
}

__device__ __forceinline__ float warpSum(float v) {
#pragma unroll
    for (int o = 16; o > 0; o >>= 1)
        v += __shfl_xor_sync(0xffffffffu, v, o);
    return v;
}

__device__ __forceinline__ float ex2f(float x) {
    float r; asm("ex2.approx.ftz.f32 %0, %1;" : "=f"(r) : "f"(x)); return r;
}
__device__ __forceinline__ float lg2f(float x) {
    float r; asm("lg2.approx.ftz.f32 %0, %1;" : "=f"(r) : "f"(x)); return r;
}

// base-2 log-add-exp: max(a,b) + log2(1 + 2^(-|a-b|)). NaN-free for finite in.
__device__ __forceinline__ float laddexp2(float a, float b) {
    float m = fmaxf(a, b);
    float t = ex2f(-fabsf(a - b));
    return m + lg2f(1.0f + t);
}

// Extract element e (0..511) of a row held distributed across the warp.
// WARP-COLLECTIVE: all 32 lanes must be active.
__device__ __forceinline__ float extract_elem(
    const float4& v0, const float4& v1, const float4& v2, const float4& v3, int e) {
    int g = (e >> 7) & 3;
    int comp = e & 3;
    int srclane = (e >> 2) & 31;
    float4 vv = (g == 0) ? v0 : (g == 1) ? v1 : (g == 2) ? v2 : v3;
    float c = (comp == 0) ? vv.x : (comp == 1) ? vv.y : (comp == 2) ? vv.z : vv.w;
    return __shfl_sync(0xffffffffu, c, srclane);
}

// Stage 1: per-(b,t,u) logsumexp over H; one row per warp; writes straight
// into the diagonal-major fused table. t==0 blocks additionally NEGF-fill
// the table cells that are never written (guards + out-of-range region).
// NO atomics, NO fences, NO block-wide syncs: pure streaming (87% DRAM).
__global__ __launch_bounds__(512, 4)
void k_lse(const float* __restrict__ x,
           const int* __restrict__ label,
           const int* __restrict__ blankp) {
    const int blk = blockIdx.x;
    const int bt = blk >> 2;                 // b*Tn + t
    const int b = bt / Tn;
    const int t = bt - b * Tn;
    const int warp = threadIdx.x >> 5;
    const int lane = threadIdx.x & 31;
    const int u = ((blk & 3) << 4) + warp;   // 0..63
    const int blank = blankp ? __ldg(blankp) : 0;

    float* const base = g_cd + (size_t)b * 256 * Un * 2;

    // --- NEGF init of unwritten cells (t==0 blocks only; disjoint writes) ---
    if (t == 0) {
#pragma unroll
        for (int h = 0; h < 2; h++) {
            int r = lane + h * 32;                 // 0..63
            int rx = (r <= u) ? r : r + 192;       // .x unwritten: [0,u] U [u+193,255]
            base[(rx * Un + u) * 2 + 0] = NEGF;
            if (u >= 1) {
                int ry = (r < u) ? r : r + 192;    // .y unwritten: [0,u-1] U [u+192,255]
                base[(ry * Un + u) * 2 + 1] = NEGF;
            }
        }
        if (u == 0) {
#pragma unroll
            for (int h = 0; h < 8; h++)            // col 0 .y: all 256 rows
                base[((lane + h * 32) * Un) * 2 + 1] = NEGF;
        }
    }

    const float4* r = reinterpret_cast<const float4*>(x)
                      + ((size_t)bt * Un + u) * (Hn / 4);
    float4 a0 = __ldcs(r + lane);
    float4 a1 = __ldcs(r + lane + 32);
    float4 a2 = __ldcs(r + lane + 64);
    float4 a3 = __ldcs(r + lane + 96);

    int lab = (u < Un - 1) ? __ldg(&label[b * (Un - 1) + u]) : 0;

    float m = fmaxf(fmaxf(fmaxf(a0.x, a0.y), fmaxf(a0.z, a0.w)),
             fmaxf(fmaxf(fmaxf(a1.x, a1.y), fmaxf(a1.z, a1.w)),
             fmaxf(fmaxf(fmaxf(a2.x, a2.y), fmaxf(a2.z, a2.w)),
                   fmaxf(fmaxf(a3.x, a3.y), fmaxf(a3.z, a3.w)))));
    m = warpMax(m);
    float s = __expf(a0.x - m) + __expf(a0.y - m) + __expf(a0.z - m) + __expf(a0.w - m)
            + __expf(a1.x - m) + __expf(a1.y - m) + __expf(a1.z - m) + __expf(a1.w - m)
            + __expf(a2.x - m) + __expf(a2.y - m) + __expf(a2.z - m) + __expf(a2.w - m)
            + __expf(a3.x - m) + __expf(a3.y - m) + __expf(a3.z - m) + __expf(a3.w - m);
    s = warpSum(s);
    float denom = m + __logf(s);

    float xb = extract_elem(a0, a1, a2, a3, blank);
    float xl = extract_elem(a0, a1, a2, a3, lab);
    if (lane == 0) {
        // lpb2[t][u] feeds cell (t+1, u): row (t+1)+u, col u, comp .x
        base[(((t + u + 1) * Un) + u) * 2 + 0] = (xb - denom) * LOG2E;
        // lpl2[t][u] feeds cell (t, u+1): row t+(u+1), col u+1, comp .y
        if (u < Un - 1)
            base[(((t + u + 1) * Un) + u + 1) * 2 + 1] = (xl - denom) * LOG2E;
    }
}

// Stage 2: uniform anti-diagonal wavefront, diagonal-major fused table.
// One block per b; 512 threads preload ONLY rows 0..dHit+1 into smem; warp 0
// runs the wavefront with 2 u-cells per lane, ONE conflict-free LDS.128 per
// lane per diagonal (software-pipelined), loop ends exactly at dHit = tl+ul.
__global__ __launch_bounds__(512, 1)
void k_alpha(const int* __restrict__ f_len,
             const int* __restrict__ y_len,
             float* __restrict__ out) {
    extern __shared__ float sm[];            // up to 256*Un*2 floats = 131072 B

    const int b = blockIdx.x;
    const int tid = threadIdx.x;

    const int tl = f_len[b] - 1;             // 95..191 (uniform per block)
    const int ul = y_len[b];                 // 32..63
    const int dHit = tl + ul;                // diagonal of the target cell

    {
        const float4* src = reinterpret_cast<const float4*>(g_cd)
                            + (size_t)b * (256 * Un * 2 / 4);
        float4* dst = reinterpret_cast<float4*>(sm);
        const int nv = (dHit + 2) * (Un * 2 / 4);   // rows 0..dHit+1 only
#pragma unroll 4
        for (int i = tid; i < nv; i += 512)
            dst[i] = src[i];
    }
    __syncthreads();

    if (tid >= 32) return;
    const int lane = tid;
    const unsigned FULL = 0xffffffffu;

    // fin_b = lpb2[tl][ul] = cell (tl+1, ul).x = row dHit+1, col ul, .x
    const float fin_b = sm[(((dHit + 1) * Un) + ul) * 2 + 0];

    const float4* row = reinterpret_cast<const float4*>(sm) + 32 + lane; // d=1
    float aA = 0.f;   // alpha2 of u=2*lane on the previous diagonal
    float aB = 0.f;   // alpha2 of u=2*lane+1

    float4 c = *row;                         // prime the pipeline (row d=1)
#pragma unroll 2
    for (int d = 1; d <= dHit; d++) {
        row += 32;
        float4 cn = *row;                    // prefetch d+1 (<= dHit+1: loaded)
        float lA = __shfl_up_sync(FULL, aB, 1);  // lane0: dead (c.y == NEGF)
        float lB = aA;
        aA = laddexp2(aA + c.x, lA + c.y);
        aB = laddexp2(aB + c.z, lB + c.w);
        c = cn;
    }

    // target cell value sits in the hit lane after the final iteration
    if (lane == (ul >> 1)) {
        float v = (ul & 1) ? aB : aA;
        out[b] = -(v + fin_b) * LN2f;
    }
}

extern "C" void kernel_launch(void* const* d_in, const int* in_sizes, int n_in,
                              void* d_out, int out_size) {
    const float* x = (const float*)d_in[0];
    const int* label = (const int*)d_in[1];
    const int* f_len = (const int*)d_in[2];
    const int* y_len = (const int*)d_in[3];
    const int* blankp = (n_in > 4) ? (const int*)d_in[4] : nullptr;

    k_lse<<<Bn * Tn * 4, 512>>>(x, label, blankp);

    const int smem = 256 * Un * 2 * (int)sizeof(float);  // 131072 B (max)
    cudaFuncSetAttribute(k_alpha, cudaFuncAttributeMaxDynamicSharedMemorySize, smem);
    k_alpha<<<Bn, 512, smem>>>(f_len, y_len, (float*)d_out);
}

// round 13
// speedup vs baseline: 1.1508x; 1.0368x over previous
#include <cuda_runtime.h>

#define Bn 16
#define Tn 192
#define Un 64
#define Hn 512
#define NEGF (-1e30f)
#define LOG2E 1.4426950408889634f
#define LN2f  0.6931471805599453f

// Diagonal-major fused table, base-2 log domain.
// Cell (t,u) lives at row d = t+u, col u, as float2:
//   .x = lpb2[t-1][u]  (the "up" transition into (t,u))
//   .y = lpl2[t][u-1]  (the "left" transition into (t,u))
// Rows 0..255; cells never written by k_lse are set to NEGF by the t==0
// blocks of k_lse itself (disjoint addresses -> no race, no extra launch).
__device__ float g_cd[Bn * 256 * Un * 2];

__device__ __forceinline__ float warpMax(float v) {
#pragma unroll
    for (int o = 16; o > 0; o >>= 1)
        v = fmaxf(v, __shfl_xor_sync(0xffffffffu, v, o));
    return v;
}

__device__ __forceinline__ float warpSum(float v) {
#pragma unroll
    for (int o = 16; o > 0; o >>= 1)
        v += __shfl_xor_sync(0xffffffffu, v, o);
    return v;
}

__device__ __forceinline__ float ex2f(float x) {
    float r; asm("ex2.approx.ftz.f32 %0, %1;" : "=f"(r) : "f"(x)); return r;
}
__device__ __forceinline__ float lg2f(float x) {
    float r; asm("lg2.approx.ftz.f32 %0, %1;" : "=f"(r) : "f"(x)); return r;
}

// base-2 log-add-exp: max(a,b) + log2(1 + 2^(-|a-b|)). NaN-free for finite in.
__device__ __forceinline__ float laddexp2(float a, float b) {
    float m = fmaxf(a, b);
    float t = ex2f(-fabsf(a - b));
    return m + lg2f(1.0f + t);
}

// Extract element e (0..511) of a row held distributed across the warp.
// WARP-COLLECTIVE: all 32 lanes must be active.
__device__ __forceinline__ float extract_elem(
    const float4& v0, const float4& v1, const float4& v2, const float4& v3, int e) {
    int g = (e >> 7) & 3;
    int comp = e & 3;
    int srclane = (e >> 2) & 31;
    float4 vv = (g == 0) ? v0 : (g == 1) ? v1 : (g == 2) ? v2 : v3;
    float c = (comp == 0) ? vv.x : (comp == 1) ? vv.y : (comp == 2) ? vv.z : vv.w;
    return __shfl_sync(0xffffffffu, c, srclane);
}

// Stage 1: per-(b,t,u) logsumexp over H; one row per warp; writes straight
// into the diagonal-major fused table. t==0 blocks additionally NEGF-fill
// the table cells that are never written (guards + out-of-range region).
// NO atomics, NO fences, NO block-wide syncs: pure streaming.
__global__ __launch_bounds__(512, 4)
void k_lse(const float* __restrict__ x,
           const int* __restrict__ label,
           const int* __restrict__ blankp) {
    const int blk = blockIdx.x;
    const int bt = blk >> 2;                 // b*Tn + t
    const int b = bt / Tn;
    const int t = bt - b * Tn;
    const int warp = threadIdx.x >> 5;
    const int lane = threadIdx.x & 31;
    const int u = ((blk & 3) << 4) + warp;   // 0..63
    const int blank = blankp ? __ldg(blankp) : 0;

    float* const base = g_cd + (size_t)b * 256 * Un * 2;

    // --- NEGF init of unwritten cells (t==0 blocks only; disjoint writes) ---
    if (t == 0) {
#pragma unroll
        for (int h = 0; h < 2; h++) {
            int r = lane + h * 32;                 // 0..63
            int rx = (r <= u) ? r : r + 192;       // .x unwritten: [0,u] U [u+193,255]
            base[(rx * Un + u) * 2 + 0] = NEGF;
            if (u >= 1) {
                int ry = (r < u) ? r : r + 192;    // .y unwritten: [0,u-1] U [u+192,255]
                base[(ry * Un + u) * 2 + 1] = NEGF;
            }
        }
        if (u == 0) {
#pragma unroll
            for (int h = 0; h < 8; h++)            // col 0 .y: all 256 rows
                base[((lane + h * 32) * Un) * 2 + 1] = NEGF;
        }
    }

    const float4* r = reinterpret_cast<const float4*>(x)
                      + ((size_t)bt * Un + u) * (Hn / 4);
    float4 a0 = __ldcs(r + lane);
    float4 a1 = __ldcs(r + lane + 32);
    float4 a2 = __ldcs(r + lane + 64);
    float4 a3 = __ldcs(r + lane + 96);

    int lab = (u < Un - 1) ? __ldg(&label[b * (Un - 1) + u]) : 0;

    float m = fmaxf(fmaxf(fmaxf(a0.x, a0.y), fmaxf(a0.z, a0.w)),
             fmaxf(fmaxf(fmaxf(a1.x, a1.y), fmaxf(a1.z, a1.w)),
             fmaxf(fmaxf(fmaxf(a2.x, a2.y), fmaxf(a2.z, a2.w)),
                   fmaxf(fmaxf(a3.x, a3.y), fmaxf(a3.z, a3.w)))));
    m = warpMax(m);
    float s = __expf(a0.x - m) + __expf(a0.y - m) + __expf(a0.z - m) + __expf(a0.w - m)
            + __expf(a1.x - m) + __expf(a1.y - m) + __expf(a1.z - m) + __expf(a1.w - m)
            + __expf(a2.x - m) + __expf(a2.y - m) + __expf(a2.z - m) + __expf(a2.w - m)
            + __expf(a3.x - m) + __expf(a3.y - m) + __expf(a3.z - m) + __expf(a3.w - m);
    s = warpSum(s);
    float denom = m + __logf(s);

    float xb = extract_elem(a0, a1, a2, a3, blank);
    float xl = extract_elem(a0, a1, a2, a3, lab);
    if (lane == 0) {
        // lpb2[t][u] feeds cell (t+1, u): row (t+1)+u, col u, comp .x
        base[(((t + u + 1) * Un) + u) * 2 + 0] = (xb - denom) * LOG2E;
        // lpl2[t][u] feeds cell (t, u+1): row t+(u+1), col u+1, comp .y
        if (u < Un - 1)
            base[(((t + u + 1) * Un) + u + 1) * 2 + 1] = (xl - denom) * LOG2E;
    }
}

// Stage 2: uniform anti-diagonal wavefront, diagonal-major fused table.
// One block per b; 512 threads preload the full 128KB table into smem with a
// COMPILE-TIME trip count (MLP-friendly); warp 0 runs the wavefront with 2
// u-cells per lane, ONE conflict-free LDS.128 per lane per diagonal
// (software-pipelined, unroll 8), loop ends exactly at dHit = tl+ul.
__global__ __launch_bounds__(512, 1)
void k_alpha(const int* __restrict__ f_len,
             const int* __restrict__ y_len,
             float* __restrict__ out) {
    extern __shared__ float sm[];            // 256*Un*2 floats = 131072 B

    const int b = blockIdx.x;
    const int tid = threadIdx.x;

    {
        const float4* src = reinterpret_cast<const float4*>(g_cd)
                            + (size_t)b * (256 * Un * 2 / 4);
        float4* dst = reinterpret_cast<float4*>(sm);
        const int nv = 256 * Un * 2 / 4;     // 8192 (compile-time)
#pragma unroll 4
        for (int i = tid; i < nv; i += 512)
            dst[i] = src[i];
    }
    __syncthreads();

    if (tid >= 32) return;
    const int lane = tid;
    const int tl = f_len[b] - 1;             // 95..191
    const int ul = y_len[b];                 // 32..63
    const int dHit = tl + ul;                // diagonal of the target cell
    const unsigned FULL = 0xffffffffu;

    // fin_b = lpb2[tl][ul] = cell (tl+1, ul).x = row dHit+1, col ul, .x
    const float fin_b = sm[(((dHit + 1) * Un) + ul) * 2 + 0];

    const float4* row = reinterpret_cast<const float4*>(sm) + 32 + lane; // d=1
    float aA = 0.f;   // alpha2 of u=2*lane on the previous diagonal
    float aB = 0.f;   // alpha2 of u=2*lane+1

    float4 c = *row;                         // prime the pipeline (row d=1)
#pragma unroll 8
    for (int d = 1; d <= dHit; d++) {
        row += 32;
        float4 cn = *row;                    // prefetch d+1 (row<=255: in-bounds)
        float lA = __shfl_up_sync(FULL, aB, 1);  // lane0: dead (c.y == NEGF)
        float lB = aA;
        aA = laddexp2(aA + c.x, lA + c.y);
        aB = laddexp2(aB + c.z, lB + c.w);
        c = cn;
    }

    // target cell value sits in the hit lane after the final iteration
    if (lane == (ul >> 1)) {
        float v = (ul & 1) ? aB : aA;
        out[b] = -(v + fin_b) * LN2f;
    }
}

extern "C" void kernel_launch(void* const* d_in, const int* in_sizes, int n_in,
                              void* d_out, int out_size) {
    const float* x = (const float*)d_in[0];
    const int* label = (const int*)d_in[1];
    const int* f_len = (const int*)d_in[2];
    const int* y_len = (const int*)d_in[3];
    const int* blankp = (n_in > 4) ? (const int*)d_in[4] : nullptr;

    k_lse<<<Bn * Tn * 4, 512>>>(x, label, blankp);

    const int smem = 256 * Un * 2 * (int)sizeof(float);  // 131072 B
    cudaFuncSetAttribute(k_alpha, cudaFuncAttributeMaxDynamicSharedMemorySize, smem);
    k_alpha<<<Bn, 512, smem>>>(f_len, y_len, (float*)d_out);
}